// round 17
// baseline (speedup 1.0000x reference)
#include <cuda_runtime.h>

// PeptidePocketConvLayer — GB300 sm_103a
//
// Inputs: d_in[0] peptide f32 [B,15,20], d_in[1] pocket i32 [B,34],
//         d_in[2] kernel f32 [20,9].  Output f32 [B,34,28].
//
//  - pocket mask periodic 9 -> agg[q] = pep[q] + (jb!=q ? pep[jb] : 0), jb=3*(q%3)
//  - peptide rows 9..14 never referenced
//  - zero-padded agg rows (logical -8..27): conv is branch-free aligned LDS.128
//  - G=16 batches/block, 9 warps; conv warp w -> q=w, lane=(i,c): p=q+9i, k0=4c
//      * agg addresses depend only on c -> 7 distinct f4/warp -> ~1 wf per LDS.128
//      * filter addresses depend only on i -> 4 distinct f4/warp -> ~1 wf
//        (raw kernel table id-indexed directly; no per-pocket gather phase)
//      * stores: per i-group 7 consecutive f4 (112B runs) -> coalesced __stcs
//  - peptide staged with cp.async.cg (global->smem direct; no STS pass)

#define NPOCK   34
#define OUT_F4  238          // 34*28/4 float4 per batch
#define PEP_F4  75           // 15*20/4 float4 per batch (global)
#define AGG_W   36           // padded agg row words: logical -8..27
#define FSTR    12           // padded kernel row words (48B, 16B-aligned)
#define G       16           // batches per block
#define NTHR    288          // 9 warps

__global__ __launch_bounds__(NTHR, 6)
void pep_pocket_conv_kernel(const float* __restrict__ pep,
                            const int*   __restrict__ pock,
                            const float* __restrict__ ker,
                            float*       __restrict__ out)
{
    __shared__ __align__(16) float4 sPepV[G * 45];        // rows 0..8 x 20 /batch
    __shared__ __align__(16) float  sAgg[G * 9 * AGG_W];  // padded agg rows
    __shared__ __align__(16) float  sKer[20 * FSTR];      // raw kernel, padded rows
    __shared__ int sId[G * NPOCK];

    const int b0 = blockIdx.x * G;
    const int t  = threadIdx.x;

    // ---- stage peptide rows 0..8 via cp.async (G*45 x 16B, no STS pass) ----
    for (int i = t; i < G * 45; i += NTHR) {
        int g = i / 45, r = i - g * 45;
        const float4* src = (const float4*)pep + (size_t)(b0 + g) * PEP_F4 + r;
        unsigned sdst = (unsigned)__cvta_generic_to_shared(&sPepV[i]);
        asm volatile("cp.async.cg.shared.global [%0], [%1], 16;\n"
                     :: "r"(sdst), "l"(src));
    }
    // ---- pocket ids + raw kernel table (tiny, plain LDG/STS) ----
    for (int i = t; i < G * NPOCK; i += NTHR) {
        int g = i / NPOCK, r = i - g * NPOCK;
        sId[i] = pock[(size_t)(b0 + g) * NPOCK + r];
    }
    if (t < 180) {
        int r = t / 9, j = t - r * 9;
        sKer[r * FSTR + j] = __ldg(ker + t);
    }
    asm volatile("cp.async.commit_group;\ncp.async.wait_group 0;\n" ::: "memory");
    __syncthreads();

    // ---- aggregates, float4-wide; every slot written exactly once ----
    // per batch: 9 rows x 9 f4-slots (slots 0,1,7,8 zero pad; 2..6 data)
    for (int s = t; s < G * 81; s += NTHR) {
        int g = s / 81, r = s - g * 81;
        int q = r / 9,  a = r - q * 9;
        float4 v = make_float4(0.f, 0.f, 0.f, 0.f);
        if (a >= 2 && a <= 6) {
            int c  = a - 2;
            int jb = 3 * (q - 3 * (q / 3));      // 3*(q%3)
            float4 u = sPepV[g * 45 + q * 5 + c];
            if (jb != q) {
                float4 w = sPepV[g * 45 + jb * 5 + c];
                u.x += w.x; u.y += w.y; u.z += w.z; u.w += w.w;
            }
            v = u;
        }
        ((float4*)sAgg)[s] = v;                  // s == g*81 + q*9 + a
    }
    __syncthreads();

    // ---- conv: warp w -> q=w; lane=(i,c): pocket p=q+9i, output f4 k0=4c ----
    {
        const int lane = t & 31;
        const int q    = t >> 5;                 // 0..8
        const int i    = lane / 7;               // 0..4 (i==4 inactive)
        const int c    = lane - i * 7;           // 0..6
        const int p    = q + 9 * i;
        const int np   = (q < 7) ? 4 : 3;        // pockets with this q (34=9*3+7)

        if (i < np) {
            const float* rowp = &sAgg[q * AGG_W + 4 * c];    // +9*AGG_W per g
            const int*   idp  = &sId[p];                      // +NPOCK per g
            float4* outV = (float4*)out + (size_t)b0 * OUT_F4 + p * 7 + c;

            #pragma unroll
            for (int g = 0; g < G; ++g) {
                // filter row by amino-acid id: 4 distinct addresses/warp -> dedup
                const float* fr = &sKer[idp[g * NPOCK] * FSTR];
                float4 f03 = *(const float4*)(fr + 0);
                float4 f47 = *(const float4*)(fr + 4);
                float  f8v = fr[8];
                float f[9] = { f03.x, f03.y, f03.z, f03.w,
                               f47.x, f47.y, f47.z, f47.w, f8v };

                // agg window: logical 4c-8..4c+3; addresses depend only on c
                float4 a0 = *(const float4*)(rowp + 0);
                float4 a1 = *(const float4*)(rowp + 4);
                float4 a2 = *(const float4*)(rowp + 8);
                float a[12] = { a0.x, a0.y, a0.z, a0.w,
                                a1.x, a1.y, a1.z, a1.w,
                                a2.x, a2.y, a2.z, a2.w };

                float o0 = 0.f, o1 = 0.f, o2 = 0.f, o3 = 0.f;
                #pragma unroll
                for (int j = 0; j < 9; ++j) {    // out[k] = sum_j f[j]*agg[k-j]
                    o0 = fmaf(f[j], a[8  - j], o0);
                    o1 = fmaf(f[j], a[9  - j], o1);
                    o2 = fmaf(f[j], a[10 - j], o2);
                    o3 = fmaf(f[j], a[11 - j], o3);
                }

                __stcs(&outV[g * OUT_F4], make_float4(o0, o1, o2, o3));

                rowp += 9 * AGG_W;
            }
        }
    }
}

extern "C" void kernel_launch(void* const* d_in, const int* in_sizes, int n_in,
                              void* d_out, int out_size)
{
    const float* pep  = (const float*)d_in[0];
    const int*   pock = (const int*)d_in[1];
    const float* ker  = (const float*)d_in[2];
    float*       out  = (float*)d_out;

    const int B = in_sizes[1] / NPOCK;   // pocket_encoding is [B, 34]

    pep_pocket_conv_kernel<<<B / G, NTHR>>>(pep, pock, ker, out);
}